// round 2
// baseline (speedup 1.0000x reference)
#include <cuda_runtime.h>
#include <cstdint>

#define N_PROP  2000
#define N_CLS   81
#define N_SORT  2048
#define PAD     300
#define MASK_F  63504      // 28*28*81
#define MASK_F4 15876      // MASK_F / 4
#define SUPP_W  64         // u32 words per suppression row (2048 bits)

// ---------------- device scratch (no allocations allowed) ----------------
__device__ float4 g_boxes[N_PROP];                 // decoded+clipped argmax-class box, original order
__device__ unsigned long long g_keys[N_PROP];      // sort keys
__device__ int    g_sorted[N_SORT];                // sorted position -> original index
__device__ float4 g_sboxes[N_PROP];                // boxes in sorted order
__device__ unsigned g_supp[N_PROP * SUPP_W];       // suppression bitmask per sorted row
__device__ int    g_keptpos[PAD];                  // sorted positions of first <=300 kept
__device__ int    g_numkept;

// ---------------- K1: per-proposal argmax / max-score / box decode ----------------
__global__ void k1_prep(const float* __restrict__ meta,
                        const float* __restrict__ deltas,
                        const float* __restrict__ props,
                        const float* __restrict__ scores) {
    int warp = (blockIdx.x * blockDim.x + threadIdx.x) >> 5;
    int lane = threadIdx.x & 31;
    if (warp >= N_PROP) return;

    const float* sc = scores + (size_t)warp * N_CLS;
    float bv = -1e30f; int bi = N_CLS; float ms = -1e30f;
    for (int c = lane; c < N_CLS; c += 32) {
        float s = sc[c];
        if (s > bv || (s == bv && c < bi)) { bv = s; bi = c; }
        if (c >= 1) ms = fmaxf(ms, s);
    }
    for (int off = 16; off; off >>= 1) {
        float ov = __shfl_down_sync(0xffffffffu, bv, off);
        int   oi = __shfl_down_sync(0xffffffffu, bi, off);
        float om = __shfl_down_sync(0xffffffffu, ms, off);
        if (ov > bv || (ov == bv && oi < bi)) { bv = ov; bi = oi; }
        ms = fmaxf(ms, om);
    }
    if (lane == 0) {
        float H = meta[0], W = meta[1], scale = meta[2];
        float x1 = props[warp*4+0] / scale, y1 = props[warp*4+1] / scale;
        float x2 = props[warp*4+2] / scale, y2 = props[warp*4+3] / scale;
        float a  = x2 - x1, b = y2 - y1;
        float cx = x1 + 0.5f*a, cy = y1 + 0.5f*b;
        const float* d = deltas + (size_t)warp * (4*N_CLS) + 4*bi;
        float pcx = d[0]*a + cx, pcy = d[1]*b + cy;
        float pw  = expf(d[2])*a, ph = expf(d[3])*b;
        float ox1 = fminf(fmaxf(pcx - 0.5f*pw, 0.f), W - 1.f);
        float oy1 = fminf(fmaxf(pcy - 0.5f*ph, 0.f), H - 1.f);
        float ox2 = fminf(fmaxf(pcx + 0.5f*pw, 0.f), W - 1.f);
        float oy2 = fminf(fmaxf(pcy + 0.5f*ph, 0.f), H - 1.f);
        g_boxes[warp] = make_float4(ox1, oy1, ox2, oy2);

        // key: score descending, index ascending on ties  == stable argsort(-score)
        unsigned u = __float_as_uint(ms);
        u = (u & 0x80000000u) ? ~u : (u | 0x80000000u);   // order-preserving map
        unsigned hi = ~u;                                  // flip for descending
        g_keys[warp] = ((unsigned long long)hi << 32) | (unsigned)warp;
    }
}

// ---------------- K2: single-block bitonic sort of 2048 u64 keys ----------------
__global__ void k2_sort() {
    __shared__ unsigned long long sk[N_SORT];
    int t = threadIdx.x;
    for (int i = t; i < N_SORT; i += 1024)
        sk[i] = (i < N_PROP) ? g_keys[i] : 0xFFFFFFFFFFFFFFFFull;
    __syncthreads();
    for (int k = 2; k <= N_SORT; k <<= 1) {
        for (int j = k >> 1; j > 0; j >>= 1) {
            for (int i = t; i < N_SORT; i += 1024) {
                int ixj = i ^ j;
                if (ixj > i) {
                    unsigned long long a = sk[i], b = sk[ixj];
                    bool up = ((i & k) == 0);
                    if (up ? (a > b) : (a < b)) { sk[i] = b; sk[ixj] = a; }
                }
            }
            __syncthreads();
        }
    }
    for (int i = t; i < N_PROP; i += 1024) {
        int idx = (int)(unsigned)(sk[i] & 0xFFFFFFFFull);
        g_sorted[i]  = idx;
        g_sboxes[i]  = g_boxes[idx];
    }
}

// ---------------- K3: suppression bit-matrix (iou > 0.5, j > i) ----------------
__global__ void k3_supp() {
    __shared__ float sx1[N_PROP], sy1[N_PROP], sx2[N_PROP], sy2[N_PROP], sar[N_PROP];
    for (int i = threadIdx.x; i < N_PROP; i += blockDim.x) {
        float4 bb = g_sboxes[i];
        sx1[i] = bb.x; sy1[i] = bb.y; sx2[i] = bb.z; sy2[i] = bb.w;
        sar[i] = fmaxf(bb.z - bb.x, 0.f) * fmaxf(bb.w - bb.y, 0.f);
    }
    __syncthreads();
    int lane = threadIdx.x & 31;
    int wid  = threadIdx.x >> 5;          // 0..7
    int base = blockIdx.x * 16;           // 16 rows per block
    for (int task = wid; task < 16 * SUPP_W; task += 8) {
        int rl = task >> 6;               // local row
        int w  = task & 63;               // word
        int ri = base + rl;
        int j  = w * 32 + lane;
        bool bit = false;
        if (j > ri && j < N_PROP) {
            float ix1 = fmaxf(sx1[ri], sx1[j]);
            float iy1 = fmaxf(sy1[ri], sy1[j]);
            float ix2 = fminf(sx2[ri], sx2[j]);
            float iy2 = fminf(sy2[ri], sy2[j]);
            float inter = fmaxf(ix2 - ix1, 0.f) * fmaxf(iy2 - iy1, 0.f);
            float uni   = fmaxf(sar[ri] + sar[j] - inter, 1e-8f);
            bit = inter > 0.5f * uni;
        }
        unsigned word = __ballot_sync(0xffffffffu, bit);
        if (lane == 0) g_supp[ri * SUPP_W + w] = word;
    }
}

// ---------------- K4: sequential greedy NMS scan, 1 warp, early exit @300 kept ----------------
__global__ void k4_nms() {
    int lane = threadIdx.x;
    unsigned rem0 = 0, rem1 = 0;          // lane owns words lane and lane+32
    unsigned b0[8], b1[8];                // depth-8 prefetch ring
    #pragma unroll
    for (int d = 0; d < 8; d++) {
        b0[d] = g_supp[d * SUPP_W + lane];
        b1[d] = g_supp[d * SUPP_W + 32 + lane];
    }
    int kc = 0;
    for (int p0 = 0; p0 < N_PROP; p0 += 8) {
        #pragma unroll
        for (int d = 0; d < 8; d++) {
            int p = p0 + d;
            unsigned m0 = b0[d], m1 = b1[d];
            int np = p + 8;
            if (np < N_PROP) {
                b0[d] = g_supp[np * SUPP_W + lane];
                b1[d] = g_supp[np * SUPP_W + 32 + lane];
            }
            if (kc < PAD) {
                int w = p >> 5;
                unsigned sel = (w < 32) ? rem0 : rem1;     // w uniform across warp
                unsigned ow  = __shfl_sync(0xffffffffu, sel, w & 31);
                if (!((ow >> (p & 31)) & 1u)) {
                    if (lane == 0) g_keptpos[kc] = p;
                    kc++;
                    rem0 |= m0; rem1 |= m1;
                }
            }
        }
        if (kc >= PAD) break;
    }
    if (lane == 0) g_numkept = kc;
}

// ---------------- K5: gather/scatter outputs (DRAM-bound, float4) ----------------
__global__ void k5_out(const float* __restrict__ scores,
                       const float* __restrict__ masks,
                       float* __restrict__ out) {
    int r  = blockIdx.y;
    int nk = g_numkept;
    int src = -1;
    if (r < nk) src = g_sorted[g_keptpos[r]];

    int c = blockIdx.x * blockDim.x + threadIdx.x;
    if (c < MASK_F4) {
        float4 v = make_float4(0.f, 0.f, 0.f, 0.f);
        if (src >= 0)
            v = reinterpret_cast<const float4*>(masks)[(size_t)src * MASK_F4 + c];
        reinterpret_cast<float4*>(out + PAD*4 + PAD*N_CLS)[(size_t)r * MASK_F4 + c] = v;
    }
    if (blockIdx.x == 0) {
        int t = threadIdx.x;
        if (t < 4) {
            float v = 0.f;
            if (src >= 0) v = reinterpret_cast<const float*>(g_boxes)[src*4 + t];
            out[r*4 + t] = v;
        } else if (t < 4 + N_CLS) {
            int cc = t - 4;
            float v = 0.f;
            if (src >= 0) v = scores[(size_t)src * N_CLS + cc];
            out[PAD*4 + r*N_CLS + cc] = v;
        }
    }
}

// ---------------- launch ----------------
extern "C" void kernel_launch(void* const* d_in, const int* in_sizes, int n_in,
                              void* d_out, int out_size) {
    const float* meta    = (const float*)d_in[0];
    const float* deltas  = (const float*)d_in[1];
    const float* props   = (const float*)d_in[2];
    const float* scores  = (const float*)d_in[3];
    const float* masks   = (const float*)d_in[4];
    float* out = (float*)d_out;

    k1_prep<<<(N_PROP * 32 + 255) / 256, 256>>>(meta, deltas, props, scores);
    k2_sort<<<1, 1024>>>();
    k3_supp<<<(N_PROP + 15) / 16, 256>>>();
    k4_nms<<<1, 32>>>();
    dim3 g5((MASK_F4 + 255) / 256, PAD);
    k5_out<<<g5, 256>>>(scores, masks, out);
}

// round 3
// speedup vs baseline: 1.1012x; 1.1012x over previous
#include <cuda_runtime.h>
#include <cstdint>

#define N_PROP  2000
#define N_CLS   81
#define N_SORT  2048
#define PAD     300
#define MASK_F  63504      // 28*28*81
#define MASK_F4 15876      // MASK_F / 4
#define SUPP_W  64         // u32 words per suppression row (2048 bits)

// ---------------- device scratch (no allocations allowed) ----------------
__device__ float4 g_boxes[N_PROP];                 // decoded+clipped argmax-class box, original order
__device__ unsigned long long g_keys[N_PROP];      // sort keys
__device__ int    g_sorted[N_SORT];                // sorted position -> original index
__device__ float4 g_sboxes[N_PROP];                // boxes in sorted order
__device__ unsigned g_supp[N_PROP * SUPP_W];       // suppression bitmask per sorted row
__device__ int    g_keptpos[PAD];                  // sorted positions of first <=300 kept
__device__ int    g_numkept;

// ---------------- K1: per-proposal argmax / max-score / box decode ----------------
__global__ void k1_prep(const float* __restrict__ meta,
                        const float* __restrict__ deltas,
                        const float* __restrict__ props,
                        const float* __restrict__ scores) {
    int warp = (blockIdx.x * blockDim.x + threadIdx.x) >> 5;
    int lane = threadIdx.x & 31;
    if (warp >= N_PROP) return;

    const float* sc = scores + (size_t)warp * N_CLS;
    float bv = -1e30f; int bi = N_CLS; float ms = -1e30f;
    for (int c = lane; c < N_CLS; c += 32) {
        float s = sc[c];
        if (s > bv || (s == bv && c < bi)) { bv = s; bi = c; }
        if (c >= 1) ms = fmaxf(ms, s);
    }
    for (int off = 16; off; off >>= 1) {
        float ov = __shfl_down_sync(0xffffffffu, bv, off);
        int   oi = __shfl_down_sync(0xffffffffu, bi, off);
        float om = __shfl_down_sync(0xffffffffu, ms, off);
        if (ov > bv || (ov == bv && oi < bi)) { bv = ov; bi = oi; }
        ms = fmaxf(ms, om);
    }
    if (lane == 0) {
        float H = meta[0], W = meta[1], scale = meta[2];
        float x1 = props[warp*4+0] / scale, y1 = props[warp*4+1] / scale;
        float x2 = props[warp*4+2] / scale, y2 = props[warp*4+3] / scale;
        float a  = x2 - x1, b = y2 - y1;
        float cx = x1 + 0.5f*a, cy = y1 + 0.5f*b;
        const float* d = deltas + (size_t)warp * (4*N_CLS) + 4*bi;
        float pcx = d[0]*a + cx, pcy = d[1]*b + cy;
        float pw  = expf(d[2])*a, ph = expf(d[3])*b;
        float ox1 = fminf(fmaxf(pcx - 0.5f*pw, 0.f), W - 1.f);
        float oy1 = fminf(fmaxf(pcy - 0.5f*ph, 0.f), H - 1.f);
        float ox2 = fminf(fmaxf(pcx + 0.5f*pw, 0.f), W - 1.f);
        float oy2 = fminf(fmaxf(pcy + 0.5f*ph, 0.f), H - 1.f);
        g_boxes[warp] = make_float4(ox1, oy1, ox2, oy2);

        // key: score descending, index ascending on ties  == stable argsort(-score)
        unsigned u = __float_as_uint(ms);
        u = (u & 0x80000000u) ? ~u : (u | 0x80000000u);   // order-preserving map
        unsigned hi = ~u;                                  // flip for descending
        g_keys[warp] = ((unsigned long long)hi << 32) | (unsigned)warp;
    }
}

// ---------------- K2: single-block bitonic sort of 2048 u64 keys ----------------
__global__ void k2_sort() {
    __shared__ unsigned long long sk[N_SORT];
    int t = threadIdx.x;
    for (int i = t; i < N_SORT; i += 1024)
        sk[i] = (i < N_PROP) ? g_keys[i] : 0xFFFFFFFFFFFFFFFFull;
    __syncthreads();
    for (int k = 2; k <= N_SORT; k <<= 1) {
        for (int j = k >> 1; j > 0; j >>= 1) {
            for (int i = t; i < N_SORT; i += 1024) {
                int ixj = i ^ j;
                if (ixj > i) {
                    unsigned long long a = sk[i], b = sk[ixj];
                    bool up = ((i & k) == 0);
                    if (up ? (a > b) : (a < b)) { sk[i] = b; sk[ixj] = a; }
                }
            }
            __syncthreads();
        }
    }
    for (int i = t; i < N_PROP; i += 1024) {
        int idx = (int)(unsigned)(sk[i] & 0xFFFFFFFFull);
        g_sorted[i]  = idx;
        g_sboxes[i]  = g_boxes[idx];
    }
}

// ---------------- K3: suppression bit-matrix (iou > 0.5, j > i) ----------------
__global__ void k3_supp() {
    __shared__ float sx1[N_PROP], sy1[N_PROP], sx2[N_PROP], sy2[N_PROP], sar[N_PROP];
    for (int i = threadIdx.x; i < N_PROP; i += blockDim.x) {
        float4 bb = g_sboxes[i];
        sx1[i] = bb.x; sy1[i] = bb.y; sx2[i] = bb.z; sy2[i] = bb.w;
        sar[i] = fmaxf(bb.z - bb.x, 0.f) * fmaxf(bb.w - bb.y, 0.f);
    }
    __syncthreads();
    int lane = threadIdx.x & 31;
    int wid  = threadIdx.x >> 5;          // 0..7
    int base = blockIdx.x * 16;           // 16 rows per block
    for (int task = wid; task < 16 * SUPP_W; task += 8) {
        int rl = task >> 6;               // local row
        int w  = task & 63;               // word
        int ri = base + rl;
        int j  = w * 32 + lane;
        bool bit = false;
        if (j > ri && j < N_PROP) {
            float ix1 = fmaxf(sx1[ri], sx1[j]);
            float iy1 = fmaxf(sy1[ri], sy1[j]);
            float ix2 = fminf(sx2[ri], sx2[j]);
            float iy2 = fminf(sy2[ri], sy2[j]);
            float inter = fmaxf(ix2 - ix1, 0.f) * fmaxf(iy2 - iy1, 0.f);
            float uni   = fmaxf(sar[ri] + sar[j] - inter, 1e-8f);
            bit = inter > 0.5f * uni;
        }
        unsigned word = __ballot_sync(0xffffffffu, bit);
        if (lane == 0) g_supp[ri * SUPP_W + w] = word;
    }
}

// ---------------- K4: sequential greedy NMS scan, 1 warp, branchless ALU chain ----------------
// Removed-set R (2048 bits) lives distributed: lane l owns words l (rem0) and l+32 (rem1).
// The word under test for the current 32-box tile is REPLICATED in curw across all lanes,
// so the per-box serial chain is pure register ALU (~5 LOP/SHF ops); the shfl that fetches
// row p's contribution to curw has load-sourced (chain-independent) input and issues early.
__global__ void k4_nms() {
    const unsigned F = 0xffffffffu;
    int lane = threadIdx.x;
    unsigned rem0 = 0, rem1 = 0;
    unsigned b0[16], b1[16];              // depth-16 prefetch ring (covers ~L2 latency)
    #pragma unroll
    for (int d = 0; d < 16; d++) {
        b0[d] = g_supp[d * SUPP_W + lane];
        b1[d] = g_supp[d * SUPP_W + 32 + lane];
    }
    int kc = 0;
    unsigned curw = 0;                    // removed word for tile 0 (R empty)
    for (int p0 = 0; p0 < N_PROP; p0 += 16) {      // N_PROP % 16 == 0
        int w = p0 >> 5;                  // constant within a 16-block
        if ((p0 & 31) == 0) {             // tile boundary: refresh replicated word
            unsigned selrem = (w < 32) ? rem0 : rem1;
            curw = __shfl_sync(F, selrem, w & 31);
        }
        #pragma unroll
        for (int d = 0; d < 16; d++) {
            int p = p0 + d;
            unsigned m0 = b0[d], m1 = b1[d];
            int np = p + 16;
            bool v = (np < N_PROP);
            b0[d] = v ? g_supp[np * SUPP_W + lane]      : 0u;
            b1[d] = v ? g_supp[np * SUPP_W + 32 + lane] : 0u;

            // row p's word w, replicated to all lanes (input is loaded data -> off-chain)
            unsigned s = __shfl_sync(F, (w < 32) ? m0 : m1, w & 31);

            int bpos = (p0 & 16) + d;                 // p & 31
            unsigned kept = (~(curw >> bpos)) & 1u;   // 1 if not removed
            unsigned mask = (unsigned)(-(int)kept);
            curw |= s  & mask;                        // serial chain: SHF+LOP+IADD+LOP+LOP
            rem0 |= m0 & mask;
            rem1 |= m1 & mask;
            if (kept && kc < PAD && lane == 0)        // single predicated store
                g_keptpos[kc] = p;
            kc += (int)kept;
        }
        if (kc >= PAD) break;
    }
    if (lane == 0) g_numkept = (kc < PAD) ? kc : PAD;
}

// ---------------- K5: gather/scatter outputs (DRAM-bound, float4) ----------------
__global__ void k5_out(const float* __restrict__ scores,
                       const float* __restrict__ masks,
                       float* __restrict__ out) {
    int r  = blockIdx.y;
    int nk = g_numkept;
    int src = -1;
    if (r < nk) src = g_sorted[g_keptpos[r]];

    int c = blockIdx.x * blockDim.x + threadIdx.x;
    if (c < MASK_F4) {
        float4 v = make_float4(0.f, 0.f, 0.f, 0.f);
        if (src >= 0)
            v = reinterpret_cast<const float4*>(masks)[(size_t)src * MASK_F4 + c];
        reinterpret_cast<float4*>(out + PAD*4 + PAD*N_CLS)[(size_t)r * MASK_F4 + c] = v;
    }
    if (blockIdx.x == 0) {
        int t = threadIdx.x;
        if (t < 4) {
            float v = 0.f;
            if (src >= 0) v = reinterpret_cast<const float*>(g_boxes)[src*4 + t];
            out[r*4 + t] = v;
        } else if (t < 4 + N_CLS) {
            int cc = t - 4;
            float v = 0.f;
            if (src >= 0) v = scores[(size_t)src * N_CLS + cc];
            out[PAD*4 + r*N_CLS + cc] = v;
        }
    }
}

// ---------------- launch ----------------
extern "C" void kernel_launch(void* const* d_in, const int* in_sizes, int n_in,
                              void* d_out, int out_size) {
    const float* meta    = (const float*)d_in[0];
    const float* deltas  = (const float*)d_in[1];
    const float* props   = (const float*)d_in[2];
    const float* scores  = (const float*)d_in[3];
    const float* masks   = (const float*)d_in[4];
    float* out = (float*)d_out;

    k1_prep<<<(N_PROP * 32 + 255) / 256, 256>>>(meta, deltas, props, scores);
    k2_sort<<<1, 1024>>>();
    k3_supp<<<(N_PROP + 15) / 16, 256>>>();
    k4_nms<<<1, 32>>>();
    dim3 g5((MASK_F4 + 255) / 256, PAD);
    k5_out<<<g5, 256>>>(scores, masks, out);
}

// round 4
// speedup vs baseline: 1.1726x; 1.0649x over previous
#include <cuda_runtime.h>
#include <cstdint>

#define N_PROP  2000
#define N_CLS   81
#define N_SORT  2048
#define PAD     300
#define MASK_F  63504      // 28*28*81
#define MASK_F4 15876      // MASK_F / 4
#define SUPP_W  64         // u32 words per suppression row (2048 bits)
#define N_TILE  63         // ceil(N_PROP/32)

// ---------------- device scratch (no allocations allowed) ----------------
__device__ float4 g_boxes[N_PROP];                 // decoded+clipped argmax-class box, original order
__device__ unsigned long long g_keys[N_PROP];      // sort keys
__device__ int    g_sorted[N_SORT];                // sorted position -> original index
__device__ float4 g_sboxes[N_PROP];                // boxes in sorted order
__device__ unsigned g_supp[N_SORT * SUPP_W];       // suppression bitmask per sorted row (rows>=N_PROP zero)
__device__ int    g_keptpos[PAD];                  // sorted positions of first <=300 kept
__device__ int    g_numkept;

// ---------------- K1: per-proposal argmax / max-score / box decode ----------------
__global__ void k1_prep(const float* __restrict__ meta,
                        const float* __restrict__ deltas,
                        const float* __restrict__ props,
                        const float* __restrict__ scores) {
    int warp = (blockIdx.x * blockDim.x + threadIdx.x) >> 5;
    int lane = threadIdx.x & 31;
    if (warp >= N_PROP) return;

    const float* sc = scores + (size_t)warp * N_CLS;
    float bv = -1e30f; int bi = N_CLS; float ms = -1e30f;
    for (int c = lane; c < N_CLS; c += 32) {
        float s = sc[c];
        if (s > bv || (s == bv && c < bi)) { bv = s; bi = c; }
        if (c >= 1) ms = fmaxf(ms, s);
    }
    for (int off = 16; off; off >>= 1) {
        float ov = __shfl_down_sync(0xffffffffu, bv, off);
        int   oi = __shfl_down_sync(0xffffffffu, bi, off);
        float om = __shfl_down_sync(0xffffffffu, ms, off);
        if (ov > bv || (ov == bv && oi < bi)) { bv = ov; bi = oi; }
        ms = fmaxf(ms, om);
    }
    if (lane == 0) {
        float H = meta[0], W = meta[1], scale = meta[2];
        float x1 = props[warp*4+0] / scale, y1 = props[warp*4+1] / scale;
        float x2 = props[warp*4+2] / scale, y2 = props[warp*4+3] / scale;
        float a  = x2 - x1, b = y2 - y1;
        float cx = x1 + 0.5f*a, cy = y1 + 0.5f*b;
        const float* d = deltas + (size_t)warp * (4*N_CLS) + 4*bi;
        float pcx = d[0]*a + cx, pcy = d[1]*b + cy;
        float pw  = expf(d[2])*a, ph = expf(d[3])*b;
        float ox1 = fminf(fmaxf(pcx - 0.5f*pw, 0.f), W - 1.f);
        float oy1 = fminf(fmaxf(pcy - 0.5f*ph, 0.f), H - 1.f);
        float ox2 = fminf(fmaxf(pcx + 0.5f*pw, 0.f), W - 1.f);
        float oy2 = fminf(fmaxf(pcy + 0.5f*ph, 0.f), H - 1.f);
        g_boxes[warp] = make_float4(ox1, oy1, ox2, oy2);

        // key: score descending, index ascending on ties  == stable argsort(-score)
        unsigned u = __float_as_uint(ms);
        u = (u & 0x80000000u) ? ~u : (u | 0x80000000u);   // order-preserving map
        unsigned hi = ~u;                                  // flip for descending
        g_keys[warp] = ((unsigned long long)hi << 32) | (unsigned)warp;
    }
}

// ---------------- K2: single-block bitonic sort of 2048 u64 keys ----------------
__global__ void k2_sort() {
    __shared__ unsigned long long sk[N_SORT];
    int t = threadIdx.x;
    for (int i = t; i < N_SORT; i += 1024)
        sk[i] = (i < N_PROP) ? g_keys[i] : 0xFFFFFFFFFFFFFFFFull;
    __syncthreads();
    for (int k = 2; k <= N_SORT; k <<= 1) {
        for (int j = k >> 1; j > 0; j >>= 1) {
            for (int i = t; i < N_SORT; i += 1024) {
                int ixj = i ^ j;
                if (ixj > i) {
                    unsigned long long a = sk[i], b = sk[ixj];
                    bool up = ((i & k) == 0);
                    if (up ? (a > b) : (a < b)) { sk[i] = b; sk[ixj] = a; }
                }
            }
            __syncthreads();
        }
    }
    for (int i = t; i < N_PROP; i += 1024) {
        int idx = (int)(unsigned)(sk[i] & 0xFFFFFFFFull);
        g_sorted[i]  = idx;
        g_sboxes[i]  = g_boxes[idx];
    }
}

// ---------------- K3: suppression bit-matrix (iou > 0.5, j > i); rows >= N_PROP zeroed ----------------
__global__ void k3_supp() {
    __shared__ float sx1[N_PROP], sy1[N_PROP], sx2[N_PROP], sy2[N_PROP], sar[N_PROP];
    for (int i = threadIdx.x; i < N_PROP; i += blockDim.x) {
        float4 bb = g_sboxes[i];
        sx1[i] = bb.x; sy1[i] = bb.y; sx2[i] = bb.z; sy2[i] = bb.w;
        sar[i] = fmaxf(bb.z - bb.x, 0.f) * fmaxf(bb.w - bb.y, 0.f);
    }
    __syncthreads();
    int lane = threadIdx.x & 31;
    int wid  = threadIdx.x >> 5;          // 0..7
    int base = blockIdx.x * 16;           // 16 rows per block (grid covers N_SORT rows)
    for (int task = wid; task < 16 * SUPP_W; task += 8) {
        int rl = task >> 6;               // local row
        int w  = task & 63;               // word
        int ri = base + rl;
        int j  = w * 32 + lane;
        bool bit = false;
        if (j > ri && j < N_PROP && ri < N_PROP) {
            float ix1 = fmaxf(sx1[ri], sx1[j]);
            float iy1 = fmaxf(sy1[ri], sy1[j]);
            float ix2 = fminf(sx2[ri], sx2[j]);
            float iy2 = fminf(sy2[ri], sy2[j]);
            float inter = fmaxf(ix2 - ix1, 0.f) * fmaxf(iy2 - iy1, 0.f);
            float uni   = fmaxf(sar[ri] + sar[j] - inter, 1e-8f);
            bit = inter > 0.5f * uni;
        }
        unsigned word = __ballot_sync(0xffffffffu, bit);
        if (lane == 0) g_supp[ri * SUPP_W + w] = word;
    }
}

// ---------------- K4: sequential greedy NMS scan — minimal ALU chain, zero in-loop branches ----------------
// Removed-set distributed: lane l owns words l (rem0) and l+32 (rem1). curw replicates the word
// under test for the current 32-box tile (tile == word). Inner loop: 2 LDG(imm-offset ring),
// 1 shfl (load-sourced input), 2 SHF + 3 LOP3. Kept positions reconstructed afterwards from the
// per-tile final curw words stashed in shared memory (warp-parallel popc/scan/enumerate).
template<bool LOW>
__device__ __forceinline__ void nms_tile(int t, int lane,
        unsigned (&b0)[16], unsigned (&b1)[16],
        unsigned &curw, unsigned &rem0, unsigned &rem1) {
    const unsigned F = 0xffffffffu;
    int p0 = t * 32;
    // refresh replicated removed word for this tile (rem complete through tile t-1)
    curw = __shfl_sync(F, LOW ? rem0 : rem1, t & 31);
    #pragma unroll
    for (int half = 0; half < 2; half++) {
        const unsigned* pp = g_supp + (size_t)(p0 + half*16 + 16) * SUPP_W + lane;
        #pragma unroll
        for (int d = 0; d < 16; d++) {
            unsigned m0 = b0[d], m1 = b1[d];
            b0[d] = pp[d * SUPP_W];                 // prefetch row p+16 (imm offsets)
            b1[d] = pp[d * SUPP_W + 32];
            unsigned s = __shfl_sync(F, LOW ? m0 : m1, t & 31);  // row p's word t, replicated
            int bpos = half*16 + d;
            // mask = ~0 if box p kept (bit bpos of curw clear), else 0
            unsigned mask = ~(unsigned)(((int)(curw << (31 - bpos))) >> 31);
            curw |= s  & mask;                      // serial chain: SHF, SHF, LOP3
            rem0 |= m0 & mask;
            rem1 |= m1 & mask;
        }
    }
}

__global__ void k4_nms() {
    __shared__ unsigned smrem[N_TILE + 1];
    int lane = threadIdx.x;
    unsigned rem0 = 0, rem1 = 0, curw = 0;
    unsigned b0[16], b1[16];
    {
        const unsigned* pp = g_supp + lane;
        #pragma unroll
        for (int d = 0; d < 16; d++) { b0[d] = pp[d*SUPP_W]; b1[d] = pp[d*SUPP_W + 32]; }
    }
    int kc = 0, ntiles = N_TILE;
    for (int t = 0; t < N_TILE; t++) {
        if (t < 32) nms_tile<true >(t, lane, b0, b1, curw, rem0, rem1);
        else        nms_tile<false>(t, lane, b0, b1, curw, rem0, rem1);
        unsigned valid = (t < 62) ? 0xffffffffu : 0xffffu;   // tile 62 covers boxes 1984..1999
        if (lane == 0) smrem[t] = curw;
        kc += __popc((~curw) & valid);
        if (kc >= PAD) { ntiles = t + 1; break; }
    }
    __syncwarp();

    // Reconstruct kept positions: popc + warp exclusive scan over tile words, enumerate bits.
    int total = 0;
    #pragma unroll
    for (int rnd = 0; rnd < 2; rnd++) {
        int idx = rnd * 32 + lane;
        unsigned valid = (idx < 62) ? 0xffffffffu : ((idx == 62) ? 0xffffu : 0u);
        unsigned kw = (idx < ntiles) ? ((~smrem[idx]) & valid) : 0u;
        int c = __popc(kw);
        int inc = c;
        #pragma unroll
        for (int o = 1; o < 32; o <<= 1) {
            int v = __shfl_up_sync(0xffffffffu, inc, o);
            if (lane >= o) inc += v;
        }
        int slot = total + inc - c;                 // exclusive prefix
        while (kw) {
            int b = __ffs(kw) - 1; kw &= kw - 1;
            if (slot < PAD) g_keptpos[slot] = idx * 32 + b;
            slot++;
        }
        total += __shfl_sync(0xffffffffu, inc, 31);
    }
    if (lane == 31) g_numkept = (total < PAD) ? total : PAD;
}

// ---------------- K5: gather/scatter outputs (DRAM-bound, float4) ----------------
__global__ void k5_out(const float* __restrict__ scores,
                       const float* __restrict__ masks,
                       float* __restrict__ out) {
    int r  = blockIdx.y;
    int nk = g_numkept;
    int src = -1;
    if (r < nk) src = g_sorted[g_keptpos[r]];

    int c = blockIdx.x * blockDim.x + threadIdx.x;
    if (c < MASK_F4) {
        float4 v = make_float4(0.f, 0.f, 0.f, 0.f);
        if (src >= 0)
            v = reinterpret_cast<const float4*>(masks)[(size_t)src * MASK_F4 + c];
        reinterpret_cast<float4*>(out + PAD*4 + PAD*N_CLS)[(size_t)r * MASK_F4 + c] = v;
    }
    if (blockIdx.x == 0) {
        int t = threadIdx.x;
        if (t < 4) {
            float v = 0.f;
            if (src >= 0) v = reinterpret_cast<const float*>(g_boxes)[src*4 + t];
            out[r*4 + t] = v;
        } else if (t < 4 + N_CLS) {
            int cc = t - 4;
            float v = 0.f;
            if (src >= 0) v = scores[(size_t)src * N_CLS + cc];
            out[PAD*4 + r*N_CLS + cc] = v;
        }
    }
}

// ---------------- launch ----------------
extern "C" void kernel_launch(void* const* d_in, const int* in_sizes, int n_in,
                              void* d_out, int out_size) {
    const float* meta    = (const float*)d_in[0];
    const float* deltas  = (const float*)d_in[1];
    const float* props   = (const float*)d_in[2];
    const float* scores  = (const float*)d_in[3];
    const float* masks   = (const float*)d_in[4];
    float* out = (float*)d_out;

    k1_prep<<<(N_PROP * 32 + 255) / 256, 256>>>(meta, deltas, props, scores);
    k2_sort<<<1, 1024>>>();
    k3_supp<<<N_SORT / 16, 256>>>();
    k4_nms<<<1, 32>>>();
    dim3 g5((MASK_F4 + 255) / 256, PAD);
    k5_out<<<g5, 256>>>(scores, masks, out);
}